// round 10
// baseline (speedup 1.0000x reference)
#include <cuda_runtime.h>
#include <cuda_bf16.h>
#include <math.h>

// ---------------------------------------------------------------------------
// AsymmetricLossCustomPriorityRankNewNegOne  (B=4096, C=9605, L=20)
// Two fully-parallel streaming kernels (block-per-row each, single memory
// epoch each) instead of warp-per-row multi-epoch:
//   A: scan y over union -> g_jmin[row] (first positive column or JINF)
//   B: wl row   -> warp0 reads priority group's ~gs floats -> loss
//      other row-> one-epoch x & y_neg scan, block reduce -> loss
// Fast path device-verified; generic slow path in kernel B.
// ---------------------------------------------------------------------------

#define MAXC 16384
#define MAXB 16384
#define JINF 0x7fffffff

__device__ unsigned            g_bits[MAXC];
__device__ unsigned long long  g_pack[MAXC];   // (bits<<32 | c)  [slow path]
__device__ int                 g_jmin[MAXB];   // first positive union col per row
__device__ int                 g_ucount;
__device__ int                 g_cmin;
__device__ int                 g_cmax;
__device__ int                 g_notfast;
__device__ int                 g_gs;           // uniform group size candidate
__device__ int                 g_is_u8;

__device__ __forceinline__ unsigned enc_f(float f) {
    unsigned u = __float_as_uint(f);
    return (u & 0x80000000u) ? ~u : (u | 0x80000000u);
}
__device__ __forceinline__ float dec_f(unsigned u) {
    return __uint_as_float((u & 0x80000000u) ? (u & 0x7fffffffu) : ~u);
}
__device__ __forceinline__ float sigmoidf_(float x) {
    return 1.0f / (1.0f + expf(-x));
}
// d = x2 - x1 + 0.05; s = sigmoid(10 d); d>0 -> 2s else s
__device__ __forceinline__ float rank_loss_(float x1, float x2) {
    float d = x2 - x1 + 0.05f;
    float s = sigmoidf_(10.0f * d);
    return (d > 0.0f) ? 2.0f * s : s;
}

// --- kernel 1: init + parallel width detect ----------------------------------
__global__ void init_kernel(float* out, int out_size,
                            const unsigned int* wl_as_u32, int n_probe) {
    __shared__ int flag;
    int t = threadIdx.x;
    if (t == 0) flag = 0;
    __syncthreads();
    for (int i = t; i < out_size; i += blockDim.x) out[i] = 0.0f;
    if (t < n_probe && wl_as_u32[t] > 1u) flag = 1;
    __syncthreads();
    if (t == 0) {
        g_is_u8   = flag;
        g_ucount  = 0;
        g_cmin    = 0x7fffffff;
        g_cmax    = -1;
        g_notfast = 0;
        g_gs      = 0;
    }
}

// --- kernel 2: per-class group bitmask + stats ---------------------------------
__global__ void build_bits_kernel(const void* wl, int C, int L) {
    __shared__ int bmin, bmax, bbad, bgs;
    if (threadIdx.x == 0) { bmin = 0x7fffffff; bmax = -1; bbad = 0; bgs = 0; }
    __syncthreads();

    int c = blockIdx.x * blockDim.x + threadIdx.x;
    unsigned b = 0;
    if (c < C) {
        if (g_is_u8) {
            const unsigned char* m = (const unsigned char*)wl;
            #pragma unroll 4
            for (int l = 0; l < L; l++)
                if (m[(size_t)l * C + c]) b |= (1u << l);
        } else {
            const int* m = (const int*)wl;
            #pragma unroll 4
            for (int l = 0; l < L; l++)
                if (m[(size_t)l * C + c]) b |= (1u << l);
        }
        g_bits[c] = b;
        if (b) {
            atomicMin(&bmin, c);
            atomicMax(&bmax, c);
            if (__popc(b) > 1) bbad = 1;
            if (b == 1u) atomicAdd(&bgs, 1);   // class belongs to group 0 only
        }
    }
    __syncthreads();
    if (threadIdx.x == 0) {
        if (bmax >= 0) { atomicMin(&g_cmin, bmin); atomicMax(&g_cmax, bmax); }
        if (bbad) g_notfast = 1;
        if (bgs)  atomicAdd(&g_gs, bgs);
    }
}

// --- kernel 3: compaction + exact fast-path verification -----------------------
__global__ void compact_kernel(int C) {
    __shared__ int woff[8];
    __shared__ int sbase;
    int c    = blockIdx.x * 256 + threadIdx.x;
    int lane = threadIdx.x & 31;
    int wid  = threadIdx.x >> 5;

    unsigned b = (c < C) ? g_bits[c] : 0u;
    unsigned ballot = __ballot_sync(0xffffffffu, b != 0u);
    if (lane == 0) woff[wid] = __popc(ballot);
    __syncthreads();
    if (threadIdx.x == 0) {
        int acc = 0;
        #pragma unroll
        for (int w = 0; w < 8; w++) { int t = woff[w]; woff[w] = acc; acc += t; }
        sbase = atomicAdd(&g_ucount, acc);
    }
    __syncthreads();
    if (b) {
        int pos = sbase + woff[wid] + __popc(ballot & ((1u << lane) - 1u));
        g_pack[pos] = ((unsigned long long)b << 32) | (unsigned)c;

        int gs = g_gs;
        if (gs > 0) {
            unsigned M = (4194304u + (unsigned)gs - 1u) / (unsigned)gs;
            unsigned j = (unsigned)(c - g_cmin);
            unsigned gm = (j * M) >> 22;
            if ((int)gm != (__ffs(b) - 1) || gm >= 32u) g_notfast = 1;
        } else {
            g_notfast = 1;
        }
    }
}

// --- kernel A: y-scan, block-per-row, one epoch ---------------------------------
__global__ __launch_bounds__(256)
void scan_y_kernel(const int* __restrict__ y, int C, int B) {
    const int row = blockIdx.x;
    if (row >= B || row >= MAXB) return;

    const int n    = g_ucount;
    const int cmin = g_cmin;
    const bool fast = (!g_notfast) && (g_cmax - cmin + 1 == n);
    if (!fast) return;                     // slow path handled in loss kernel

    __shared__ int sJ;
    if (threadIdx.x == 0) sJ = JINF;
    __syncthreads();

    const long long base = (long long)row * C + cmin;
    const int* __restrict__ yr = y + base;

    int p = (int)((4 - (base & 3)) & 3);
    if (p > n) p = n;
    const int nv = (n - p) >> 2;
    const int ts = p + 4 * nv;
    const int ntail = n - ts;

    if (threadIdx.x < p && __ldg(yr + threadIdx.x))
        atomicMin(&sJ, threadIdx.x);
    for (int i = threadIdx.x; i < nv; i += 256) {
        const int4 yv = __ldg((const int4*)(yr + p + 4 * i));
        if (yv.x | yv.y | yv.z | yv.w) {
            const int j0 = p + 4 * i;
            int j;
            if      (yv.x) j = j0;
            else if (yv.y) j = j0 + 1;
            else if (yv.z) j = j0 + 2;
            else           j = j0 + 3;
            atomicMin(&sJ, j);
        }
    }
    if (threadIdx.x < ntail && __ldg(yr + ts + threadIdx.x))
        atomicMin(&sJ, ts + threadIdx.x);

    __syncthreads();
    if (threadIdx.x == 0) g_jmin[row] = sJ;
}

// --- kernel B: loss, block-per-row, one epoch ------------------------------------
__global__ __launch_bounds__(256)
void row_loss_kernel(const float* __restrict__ x,
                     const int*   __restrict__ y,
                     const int*   __restrict__ yneg,
                     int C, int B, float* __restrict__ out) {
    const int row = blockIdx.x;
    if (row >= B) return;

    const int n    = g_ucount;
    const int cmin = g_cmin;
    const bool fast = (!g_notfast) && (g_cmax - cmin + 1 == n) && (row < MAXB);

    if (fast) {
        const int jmin = g_jmin[row];
        const long long base = (long long)row * C + cmin;
        const float* __restrict__ xr  = x    + base;
        const int*   __restrict__ ynr = yneg + base;

        if (jmin != JINF) {
            // ---- wl row: warp 0 reads the priority group's x ----
            if (threadIdx.x < 32) {
                const int gs = g_gs;
                const unsigned M = (4194304u + (unsigned)gs - 1u) / (unsigned)gs;
                const int fl = (int)(((unsigned)jmin * M) >> 22);
                const int j0 = fl * gs;
                float m = -1e30f;
                for (int t = threadIdx.x; t < gs; t += 32) {
                    const int j = j0 + t;
                    if (j < n) m = fmaxf(m, __ldg(xr + j));
                }
                #pragma unroll
                for (int off = 16; off > 0; off >>= 1)
                    m = fmaxf(m, __shfl_xor_sync(0xffffffffu, m, off));
                if (threadIdx.x == 0)
                    atomicAdd(out, rank_loss_(sigmoidf_(m), 0.5f));
            }
            return;
        }

        // ---- other row: single-epoch x & y_neg scan ----
        __shared__ unsigned sNon, sWrong;
        if (threadIdx.x == 0) { sNon = enc_f(-1e30f); sWrong = enc_f(-1e30f); }
        __syncthreads();

        int p = (int)((4 - (base & 3)) & 3);
        if (p > n) p = n;
        const int nv = (n - p) >> 2;
        const int ts = p + 4 * nv;
        const int ntail = n - ts;

        float mN = -1e30f, mW = -1e30f;
        if (threadIdx.x < p) {
            const float xv = __ldg(xr + threadIdx.x);
            mN = fmaxf(mN, xv);
            mW = fmaxf(mW, __ldg(ynr + threadIdx.x) ? xv : -1e30f);
        }
        if (threadIdx.x < ntail) {
            const int j = ts + threadIdx.x;
            const float xv = __ldg(xr + j);
            mN = fmaxf(mN, xv);
            mW = fmaxf(mW, __ldg(ynr + j) ? xv : -1e30f);
        }
        for (int i = threadIdx.x; i < nv; i += 256) {
            const int j0 = p + 4 * i;
            const float4 xv  = __ldg((const float4*)(xr  + j0));
            const int4   ynv = __ldg((const int4*)  (ynr + j0));
            mN = fmaxf(mN, fmaxf(fmaxf(xv.x, xv.y), fmaxf(xv.z, xv.w)));
            mW = fmaxf(mW, ynv.x ? xv.x : -1e30f);
            mW = fmaxf(mW, ynv.y ? xv.y : -1e30f);
            mW = fmaxf(mW, ynv.z ? xv.z : -1e30f);
            mW = fmaxf(mW, ynv.w ? xv.w : -1e30f);
        }
        #pragma unroll
        for (int off = 16; off > 0; off >>= 1) {
            mN = fmaxf(mN, __shfl_xor_sync(0xffffffffu, mN, off));
            mW = fmaxf(mW, __shfl_xor_sync(0xffffffffu, mW, off));
        }
        if ((threadIdx.x & 31) == 0) {
            atomicMax(&sNon,   enc_f(mN));
            atomicMax(&sWrong, enc_f(mW));
        }
        __syncthreads();
        if (threadIdx.x == 0) {
            atomicAdd(out, 0.5f * rank_loss_(0.5f, sigmoidf_(dec_f(sNon)))
                         + 0.5f * rank_loss_(0.5f, sigmoidf_(dec_f(sWrong))));
        }
        return;
    }

    // ---------------- generic slow path (block-per-row) ----------------
    {
        const unsigned KNEG = enc_f(-1e30f);
        __shared__ unsigned sG[32];
        __shared__ unsigned sPres, sNon, sWrong;
        if (threadIdx.x < 32) sG[threadIdx.x] = KNEG;
        if (threadIdx.x == 0) { sPres = 0u; sNon = KNEG; sWrong = KNEG; }
        __syncthreads();

        unsigned locNon = KNEG, locWrong = KNEG, locPres = 0u;
        for (int i = threadIdx.x; i < n; i += 256) {
            const unsigned long long pk = g_pack[i];
            const int c         = (int)(pk & 0xffffffffull);
            const unsigned bits = (unsigned)(pk >> 32);
            const long long o = (long long)row * C + c;
            const float xv = __ldg(x + o);
            const unsigned key = enc_f(xv);
            locNon = max(locNon, key);
            if (__ldg(yneg + o) != 0) locWrong = max(locWrong, key);
            if (__ldg(y    + o) != 0) locPres |= bits;
            unsigned bb = bits;
            while (bb) {
                const int l = __ffs(bb) - 1;
                bb &= bb - 1u;
                atomicMax(&sG[l], key);
            }
        }
        #pragma unroll
        for (int off = 16; off > 0; off >>= 1) {
            locNon   = max(locNon,   __shfl_xor_sync(0xffffffffu, locNon,   off));
            locWrong = max(locWrong, __shfl_xor_sync(0xffffffffu, locWrong, off));
            locPres |= __shfl_xor_sync(0xffffffffu, locPres, off);
        }
        if ((threadIdx.x & 31) == 0) {
            atomicMax(&sNon, locNon);
            atomicMax(&sWrong, locWrong);
            atomicOr(&sPres, locPres);
        }
        __syncthreads();
        if (threadIdx.x == 0) {
            float loss;
            if (sPres) {
                const int fl = __ffs(sPres) - 1;
                loss = rank_loss_(sigmoidf_(dec_f(sG[fl])), 0.5f);
            } else {
                loss = 0.5f * rank_loss_(0.5f, sigmoidf_(dec_f(sNon)))
                     + 0.5f * rank_loss_(0.5f, sigmoidf_(dec_f(sWrong)));
            }
            atomicAdd(out, loss);
        }
    }
}

// ---------------------------------------------------------------------------
extern "C" void kernel_launch(void* const* d_in, const int* in_sizes, int n_in,
                              void* d_out, int out_size) {
    const float* x    = (const float*)d_in[0];
    const int*   y    = (const int*)d_in[1];
    const int*   yneg = (const int*)d_in[2];
    const void*  wl   = d_in[3];

    const int C = 9605;
    const int L = in_sizes[3] / C;            // 20
    const int B = in_sizes[0] / C;            // 4096

    float* out = (float*)d_out;

    init_kernel<<<1, 256>>>(out, out_size, (const unsigned int*)wl, 256);
    build_bits_kernel<<<(C + 255) / 256, 256>>>(wl, C, L);
    compact_kernel<<<(C + 255) / 256, 256>>>(C);
    scan_y_kernel<<<B, 256>>>(y, C, B);
    row_loss_kernel<<<B, 256>>>(x, y, yneg, C, B, out);
}

// round 11
// speedup vs baseline: 1.3401x; 1.3401x over previous
#include <cuda_runtime.h>
#include <cuda_bf16.h>
#include <math.h>

// ---------------------------------------------------------------------------
// AsymmetricLossCustomPriorityRankNewNegOne  (B=4096, C=9605, L=20)
// Two warp-per-row single-epoch streaming kernels, all row-warps resident in
// ONE wave (512 blocks x 256 threads):
//   A: each warp batches ALL its y loads -> g_jmin[row]
//   B: wl row  -> warp reads priority group's ~gs floats
//      other   -> one batched epoch over x & y_neg
// Fast path device-verified; generic slow path kept in kernel B.
// ---------------------------------------------------------------------------

#define MAXC 16384
#define MAXB 16384
#define JINF 0x7fffffff

__device__ unsigned            g_bits[MAXC];
__device__ unsigned long long  g_pack[MAXC];   // (bits<<32 | c)  [slow path]
__device__ int                 g_jmin[MAXB];   // first positive union col per row
__device__ int                 g_ucount;
__device__ int                 g_cmin;
__device__ int                 g_cmax;
__device__ int                 g_notfast;
__device__ int                 g_gs;           // uniform group size candidate
__device__ int                 g_is_u8;

__device__ __forceinline__ unsigned enc_f(float f) {
    unsigned u = __float_as_uint(f);
    return (u & 0x80000000u) ? ~u : (u | 0x80000000u);
}
__device__ __forceinline__ float dec_f(unsigned u) {
    return __uint_as_float((u & 0x80000000u) ? (u & 0x7fffffffu) : ~u);
}
__device__ __forceinline__ float sigmoidf_(float x) {
    return 1.0f / (1.0f + expf(-x));
}
// d = x2 - x1 + 0.05; s = sigmoid(10 d); d>0 -> 2s else s
__device__ __forceinline__ float rank_loss_(float x1, float x2) {
    float d = x2 - x1 + 0.05f;
    float s = sigmoidf_(10.0f * d);
    return (d > 0.0f) ? 2.0f * s : s;
}

// --- kernel 1: init + parallel width detect ----------------------------------
__global__ void init_kernel(float* out, int out_size,
                            const unsigned int* wl_as_u32, int n_probe) {
    __shared__ int flag;
    int t = threadIdx.x;
    if (t == 0) flag = 0;
    __syncthreads();
    for (int i = t; i < out_size; i += blockDim.x) out[i] = 0.0f;
    if (t < n_probe && wl_as_u32[t] > 1u) flag = 1;
    __syncthreads();
    if (t == 0) {
        g_is_u8   = flag;
        g_ucount  = 0;
        g_cmin    = 0x7fffffff;
        g_cmax    = -1;
        g_notfast = 0;
        g_gs      = 0;
    }
}

// --- kernel 2: per-class group bitmask + stats ---------------------------------
__global__ void build_bits_kernel(const void* wl, int C, int L) {
    __shared__ int bmin, bmax, bbad, bgs;
    if (threadIdx.x == 0) { bmin = 0x7fffffff; bmax = -1; bbad = 0; bgs = 0; }
    __syncthreads();

    int c = blockIdx.x * blockDim.x + threadIdx.x;
    unsigned b = 0;
    if (c < C) {
        if (g_is_u8) {
            const unsigned char* m = (const unsigned char*)wl;
            #pragma unroll 4
            for (int l = 0; l < L; l++)
                if (m[(size_t)l * C + c]) b |= (1u << l);
        } else {
            const int* m = (const int*)wl;
            #pragma unroll 4
            for (int l = 0; l < L; l++)
                if (m[(size_t)l * C + c]) b |= (1u << l);
        }
        g_bits[c] = b;
        if (b) {
            atomicMin(&bmin, c);
            atomicMax(&bmax, c);
            if (__popc(b) > 1) bbad = 1;
            if (b == 1u) atomicAdd(&bgs, 1);
        }
    }
    __syncthreads();
    if (threadIdx.x == 0) {
        if (bmax >= 0) { atomicMin(&g_cmin, bmin); atomicMax(&g_cmax, bmax); }
        if (bbad) g_notfast = 1;
        if (bgs)  atomicAdd(&g_gs, bgs);
    }
}

// --- kernel 3: compaction + exact fast-path verification -----------------------
__global__ void compact_kernel(int C) {
    __shared__ int woff[8];
    __shared__ int sbase;
    int c    = blockIdx.x * 256 + threadIdx.x;
    int lane = threadIdx.x & 31;
    int wid  = threadIdx.x >> 5;

    unsigned b = (c < C) ? g_bits[c] : 0u;
    unsigned ballot = __ballot_sync(0xffffffffu, b != 0u);
    if (lane == 0) woff[wid] = __popc(ballot);
    __syncthreads();
    if (threadIdx.x == 0) {
        int acc = 0;
        #pragma unroll
        for (int w = 0; w < 8; w++) { int t = woff[w]; woff[w] = acc; acc += t; }
        sbase = atomicAdd(&g_ucount, acc);
    }
    __syncthreads();
    if (b) {
        int pos = sbase + woff[wid] + __popc(ballot & ((1u << lane) - 1u));
        g_pack[pos] = ((unsigned long long)b << 32) | (unsigned)c;

        int gs = g_gs;
        if (gs > 0) {
            unsigned M = (4194304u + (unsigned)gs - 1u) / (unsigned)gs;
            unsigned j = (unsigned)(c - g_cmin);
            unsigned gm = (j * M) >> 22;
            if ((int)gm != (__ffs(b) - 1) || gm >= 32u) g_notfast = 1;
        } else {
            g_notfast = 1;
        }
    }
}

// --- kernel A: warp-per-row y-scan, one batched epoch ---------------------------
__global__ __launch_bounds__(256, 3)
void scan_y_kernel(const int* __restrict__ y, int C, int B) {
    const int lane = threadIdx.x & 31;
    const int wid  = threadIdx.x >> 5;
    const int row  = wid * gridDim.x + blockIdx.x;   // strided: mix wl/other
    if (row >= B || row >= MAXB) return;

    const int n    = g_ucount;
    const int cmin = g_cmin;
    if (g_notfast || (g_cmax - cmin + 1 != n)) return;  // slow path elsewhere

    const long long base = (long long)row * C + cmin;
    const int* __restrict__ yr = y + base;

    int p = (int)((4 - (base & 3)) & 3);
    if (p > n) p = n;
    const int nv = (n - p) >> 2;
    const int ts = p + 4 * nv;
    const int ntail = n - ts;

    int jmin = JINF;

    for (int b0 = 0; b0 < nv; b0 += 256) {
        int4 yv[8];
        #pragma unroll
        for (int k = 0; k < 8; k++) {
            const int i = b0 + lane + k * 32;
            yv[k] = (i < nv) ? __ldg((const int4*)(yr + p + 4 * i))
                             : make_int4(0, 0, 0, 0);
        }
        #pragma unroll
        for (int k = 0; k < 8; k++) {
            const int i = b0 + lane + k * 32;
            if ((yv[k].x | yv[k].y | yv[k].z | yv[k].w) && jmin == JINF && i < nv) {
                const int j0 = p + 4 * i;
                if      (yv[k].x) jmin = j0;
                else if (yv[k].y) jmin = j0 + 1;
                else if (yv[k].z) jmin = j0 + 2;
                else              jmin = j0 + 3;
            }
        }
        if (__any_sync(0xffffffffu, jmin != JINF)) break;
    }
    // peel and tail (scalar, same epoch scale)
    if (lane < p && __ldg(yr + lane) && lane < jmin) jmin = lane;
    if (lane < ntail && __ldg(yr + ts + lane)) jmin = min(jmin, ts + lane);

    #pragma unroll
    for (int off = 16; off > 0; off >>= 1)
        jmin = min(jmin, __shfl_xor_sync(0xffffffffu, jmin, off));

    if (lane == 0) g_jmin[row] = jmin;
}

// --- kernel B: warp-per-row loss, one batched epoch -----------------------------
__global__ __launch_bounds__(256, 2)
void row_loss_kernel(const float* __restrict__ x,
                     const int*   __restrict__ y,
                     const int*   __restrict__ yneg,
                     int C, int B, float* __restrict__ out) {
    __shared__ float sSum;
    __shared__ unsigned sG[8][32];           // slow path per-warp group maxes

    const int lane = threadIdx.x & 31;
    const int wid  = threadIdx.x >> 5;
    const int row  = wid * gridDim.x + blockIdx.x;

    if (threadIdx.x == 0) sSum = 0.0f;
    __syncthreads();

    const int n    = g_ucount;
    const int cmin = g_cmin;
    const bool fast = (!g_notfast) && (g_cmax - cmin + 1 == n);

    float warp_loss = 0.0f;

    if (row < B && fast && row < MAXB) {
        const int jmin = g_jmin[row];
        const long long base = (long long)row * C + cmin;
        const float* __restrict__ xr  = x    + base;
        const int*   __restrict__ ynr = yneg + base;

        if (jmin != JINF) {
            // ---- wl row: read the priority group's x (gs floats) ----
            const int gs = g_gs;
            const unsigned M = (4194304u + (unsigned)gs - 1u) / (unsigned)gs;
            const int fl = (int)(((unsigned)jmin * M) >> 22);
            const int j0 = fl * gs;
            float m = -1e30f;
            for (int t = lane; t < gs; t += 32) {
                const int j = j0 + t;
                if (j < n) m = fmaxf(m, __ldg(xr + j));
            }
            #pragma unroll
            for (int off = 16; off > 0; off >>= 1)
                m = fmaxf(m, __shfl_xor_sync(0xffffffffu, m, off));
            warp_loss = rank_loss_(sigmoidf_(m), 0.5f);
        } else {
            // ---- other row: single batched epoch over x & y_neg ----
            int p = (int)((4 - (base & 3)) & 3);
            if (p > n) p = n;
            const int nv = (n - p) >> 2;
            const int ts = p + 4 * nv;
            const int ntail = n - ts;

            float mN = -1e30f, mW = -1e30f;
            if (lane < p) {
                const float xv = __ldg(xr + lane);
                mN = fmaxf(mN, xv);
                mW = fmaxf(mW, __ldg(ynr + lane) ? xv : -1e30f);
            }
            if (lane < ntail) {
                const int j = ts + lane;
                const float xv = __ldg(xr + j);
                mN = fmaxf(mN, xv);
                mW = fmaxf(mW, __ldg(ynr + j) ? xv : -1e30f);
            }
            for (int b0 = 0; b0 < nv; b0 += 256) {
                float4 xv[8];
                int4   nvv[8];
                #pragma unroll
                for (int k = 0; k < 8; k++) {
                    const int i = b0 + lane + k * 32;
                    const int j0 = p + 4 * i;
                    if (i < nv) {
                        xv[k]  = __ldg((const float4*)(xr  + j0));
                        nvv[k] = __ldg((const int4*)  (ynr + j0));
                    } else {
                        xv[k]  = make_float4(-1e30f, -1e30f, -1e30f, -1e30f);
                        nvv[k] = make_int4(0, 0, 0, 0);
                    }
                }
                #pragma unroll
                for (int k = 0; k < 8; k++) {
                    mN = fmaxf(mN, fmaxf(fmaxf(xv[k].x, xv[k].y),
                                         fmaxf(xv[k].z, xv[k].w)));
                    mW = fmaxf(mW, nvv[k].x ? xv[k].x : -1e30f);
                    mW = fmaxf(mW, nvv[k].y ? xv[k].y : -1e30f);
                    mW = fmaxf(mW, nvv[k].z ? xv[k].z : -1e30f);
                    mW = fmaxf(mW, nvv[k].w ? xv[k].w : -1e30f);
                }
            }
            #pragma unroll
            for (int off = 16; off > 0; off >>= 1) {
                mN = fmaxf(mN, __shfl_xor_sync(0xffffffffu, mN, off));
                mW = fmaxf(mW, __shfl_xor_sync(0xffffffffu, mW, off));
            }
            warp_loss = 0.5f * rank_loss_(0.5f, sigmoidf_(mN))
                      + 0.5f * rank_loss_(0.5f, sigmoidf_(mW));
        }
    } else if (row < B) {
        // ---------------- generic slow path (warp-per-row) ----------------
        const unsigned KNEG = enc_f(-1e30f);
        sG[wid][lane] = KNEG;
        __syncwarp();

        unsigned locNon = KNEG, locWrong = KNEG, locPres = 0u;
        for (int i = lane; i < n; i += 32) {
            const unsigned long long pk = g_pack[i];
            const int c         = (int)(pk & 0xffffffffull);
            const unsigned bits = (unsigned)(pk >> 32);
            const long long o = (long long)row * C + c;
            const float xv = __ldg(x + o);
            const unsigned key = enc_f(xv);
            locNon = max(locNon, key);
            if (__ldg(yneg + o) != 0) locWrong = max(locWrong, key);
            if (__ldg(y    + o) != 0) locPres |= bits;
            unsigned bb = bits;
            while (bb) {
                const int l = __ffs(bb) - 1;
                bb &= bb - 1u;
                atomicMax(&sG[wid][l], key);
            }
        }
        #pragma unroll
        for (int off = 16; off > 0; off >>= 1) {
            locNon   = max(locNon,   __shfl_xor_sync(0xffffffffu, locNon,   off));
            locWrong = max(locWrong, __shfl_xor_sync(0xffffffffu, locWrong, off));
            locPres |= __shfl_xor_sync(0xffffffffu, locPres, off);
        }
        __syncwarp();
        if (lane == 0) {
            if (locPres) {
                const int fl = __ffs(locPres) - 1;
                warp_loss = rank_loss_(sigmoidf_(dec_f(sG[wid][fl])), 0.5f);
            } else {
                warp_loss = 0.5f * rank_loss_(0.5f, sigmoidf_(dec_f(locNon)))
                          + 0.5f * rank_loss_(0.5f, sigmoidf_(dec_f(locWrong)));
            }
        }
    }

    if (lane == 0 && row < B) atomicAdd(&sSum, warp_loss);
    __syncthreads();
    if (threadIdx.x == 0) atomicAdd(out, sSum);
}

// ---------------------------------------------------------------------------
extern "C" void kernel_launch(void* const* d_in, const int* in_sizes, int n_in,
                              void* d_out, int out_size) {
    const float* x    = (const float*)d_in[0];
    const int*   y    = (const int*)d_in[1];
    const int*   yneg = (const int*)d_in[2];
    const void*  wl   = d_in[3];

    const int C = 9605;
    const int L = in_sizes[3] / C;            // 20
    const int B = in_sizes[0] / C;            // 4096

    float* out = (float*)d_out;

    const int nblocks = (B + 7) / 8;          // 512: all row-warps in one wave

    init_kernel<<<1, 256>>>(out, out_size, (const unsigned int*)wl, 256);
    build_bits_kernel<<<(C + 255) / 256, 256>>>(wl, C, L);
    compact_kernel<<<(C + 255) / 256, 256>>>(C);
    scan_y_kernel<<<nblocks, 256>>>(y, C, B);
    row_loss_kernel<<<nblocks, 256>>>(x, y, yneg, C, B, out);
}

// round 12
// speedup vs baseline: 1.4804x; 1.1047x over previous
#include <cuda_runtime.h>
#include <cuda_bf16.h>
#include <math.h>

// ---------------------------------------------------------------------------
// AsymmetricLossCustomPriorityRankNewNegOne  (B=4096, C=9605, L=20)
// Warp-per-row, ONE speculative fused epoch (y + x together, 16 loads/lane):
//   wl row   -> priority-group max computed from the register-held x (0 extra loads)
//   other row-> mN from registers; one extra epoch for yneg -> mW
// Fast path device-verified; generic slow path kept.
// ---------------------------------------------------------------------------

#define MAXC 16384
#define JINF 0x7fffffff
#define NCH  8          // int4/float4 chunks per lane (covers 1024 cols/warp)

__device__ unsigned            g_bits[MAXC];
__device__ unsigned long long  g_pack[MAXC];   // (bits<<32 | c)  [slow path]
__device__ int                 g_ucount;
__device__ int                 g_cmin;
__device__ int                 g_cmax;
__device__ int                 g_notfast;
__device__ int                 g_gs;           // uniform group size candidate
__device__ int                 g_is_u8;

__device__ __forceinline__ unsigned enc_f(float f) {
    unsigned u = __float_as_uint(f);
    return (u & 0x80000000u) ? ~u : (u | 0x80000000u);
}
__device__ __forceinline__ float dec_f(unsigned u) {
    return __uint_as_float((u & 0x80000000u) ? (u & 0x7fffffffu) : ~u);
}
__device__ __forceinline__ float sigmoidf_(float x) {
    return 1.0f / (1.0f + expf(-x));
}
// d = x2 - x1 + 0.05; s = sigmoid(10 d); d>0 -> 2s else s
__device__ __forceinline__ float rank_loss_(float x1, float x2) {
    float d = x2 - x1 + 0.05f;
    float s = sigmoidf_(10.0f * d);
    return (d > 0.0f) ? 2.0f * s : s;
}

// --- kernel 1: init + parallel width detect ----------------------------------
__global__ void init_kernel(float* out, int out_size,
                            const unsigned int* wl_as_u32, int n_probe) {
    __shared__ int flag;
    int t = threadIdx.x;
    if (t == 0) flag = 0;
    __syncthreads();
    for (int i = t; i < out_size; i += blockDim.x) out[i] = 0.0f;
    if (t < n_probe && wl_as_u32[t] > 1u) flag = 1;
    __syncthreads();
    if (t == 0) {
        g_is_u8   = flag;
        g_ucount  = 0;
        g_cmin    = 0x7fffffff;
        g_cmax    = -1;
        g_notfast = 0;
        g_gs      = 0;
    }
}

// --- kernel 2: per-class group bitmask + stats ---------------------------------
__global__ void build_bits_kernel(const void* wl, int C, int L) {
    __shared__ int bmin, bmax, bbad, bgs;
    if (threadIdx.x == 0) { bmin = 0x7fffffff; bmax = -1; bbad = 0; bgs = 0; }
    __syncthreads();

    int c = blockIdx.x * blockDim.x + threadIdx.x;
    unsigned b = 0;
    if (c < C) {
        if (g_is_u8) {
            const unsigned char* m = (const unsigned char*)wl;
            #pragma unroll 4
            for (int l = 0; l < L; l++)
                if (m[(size_t)l * C + c]) b |= (1u << l);
        } else {
            const int* m = (const int*)wl;
            #pragma unroll 4
            for (int l = 0; l < L; l++)
                if (m[(size_t)l * C + c]) b |= (1u << l);
        }
        g_bits[c] = b;
        if (b) {
            atomicMin(&bmin, c);
            atomicMax(&bmax, c);
            if (__popc(b) > 1) bbad = 1;
            if (b == 1u) atomicAdd(&bgs, 1);
        }
    }
    __syncthreads();
    if (threadIdx.x == 0) {
        if (bmax >= 0) { atomicMin(&g_cmin, bmin); atomicMax(&g_cmax, bmax); }
        if (bbad) g_notfast = 1;
        if (bgs)  atomicAdd(&g_gs, bgs);
    }
}

// --- kernel 3: compaction + exact fast-path verification -----------------------
__global__ void compact_kernel(int C) {
    __shared__ int woff[8];
    __shared__ int sbase;
    int c    = blockIdx.x * 256 + threadIdx.x;
    int lane = threadIdx.x & 31;
    int wid  = threadIdx.x >> 5;

    unsigned b = (c < C) ? g_bits[c] : 0u;
    unsigned ballot = __ballot_sync(0xffffffffu, b != 0u);
    if (lane == 0) woff[wid] = __popc(ballot);
    __syncthreads();
    if (threadIdx.x == 0) {
        int acc = 0;
        #pragma unroll
        for (int w = 0; w < 8; w++) { int t = woff[w]; woff[w] = acc; acc += t; }
        sbase = atomicAdd(&g_ucount, acc);
    }
    __syncthreads();
    if (b) {
        int pos = sbase + woff[wid] + __popc(ballot & ((1u << lane) - 1u));
        g_pack[pos] = ((unsigned long long)b << 32) | (unsigned)c;

        int gs = g_gs;
        if (gs > 0) {
            unsigned M = (4194304u + (unsigned)gs - 1u) / (unsigned)gs;
            unsigned j = (unsigned)(c - g_cmin);
            unsigned gm = (j * M) >> 22;
            if ((int)gm != (__ffs(b) - 1) || gm >= 32u) g_notfast = 1;
        } else {
            g_notfast = 1;
        }
    }
}

// --- kernel 4: warp-per-row fused loss -------------------------------------------
__global__ __launch_bounds__(128, 5)
void row_loss_kernel(const float* __restrict__ x,
                     const int*   __restrict__ y,
                     const int*   __restrict__ yneg,
                     int C, int B, float* __restrict__ out) {
    __shared__ float sSum;
    __shared__ unsigned sG[4][32];           // slow path per-warp group maxes

    const int lane = threadIdx.x & 31;
    const int wid  = threadIdx.x >> 5;
    const int row  = wid * gridDim.x + blockIdx.x;   // strided: mix wl/other

    if (threadIdx.x == 0) sSum = 0.0f;
    __syncthreads();

    const int n    = g_ucount;
    const int cmin = g_cmin;
    const bool fast = (!g_notfast) && (g_cmax - cmin + 1 == n);

    float warp_loss = 0.0f;

    if (row < B && fast) {
        const int gs = g_gs;
        const unsigned M = (4194304u + (unsigned)gs - 1u) / (unsigned)gs;
        const long long base = (long long)row * C + cmin;
        const float* __restrict__ xr  = x    + base;
        const int*   __restrict__ yr  = y    + base;
        const int*   __restrict__ ynr = yneg + base;

        int p = (int)((4 - (base & 3)) & 3);
        if (p > n) p = n;
        const int nv = (n - p) >> 2;          // vec4 chunks
        const int nvr = nv < (NCH * 32) ? nv : (NCH * 32);   // register-covered
        const int ts = p + 4 * nv;
        const int ntail = n - ts;

        // ============ fused epoch: y + x, all loads in flight ===============
        int4   yv[NCH];
        float4 xv[NCH];
        const int   ypeel = (lane < p) ? __ldg(yr + lane) : 0;
        const float xpeel = (lane < p) ? __ldg(xr + lane) : -1e30f;
        const int   ytail = (lane < ntail) ? __ldg(yr + ts + lane) : 0;
        const float xtail = (lane < ntail) ? __ldg(xr + ts + lane) : -1e30f;
        #pragma unroll
        for (int k = 0; k < NCH; k++) {
            const int i = lane + k * 32;
            if (i < nvr) {
                yv[k] = __ldg((const int4*)  (yr + p + 4 * i));
                xv[k] = __ldg((const float4*)(xr + p + 4 * i));
            } else {
                yv[k] = make_int4(0, 0, 0, 0);
                xv[k] = make_float4(-1e30f, -1e30f, -1e30f, -1e30f);
            }
        }

        // first positive column
        int jmin = JINF;
        #pragma unroll
        for (int k = 0; k < NCH; k++) {
            if ((yv[k].x | yv[k].y | yv[k].z | yv[k].w) && jmin == JINF) {
                const int j0 = p + 4 * (lane + k * 32);
                if      (yv[k].x) jmin = j0;
                else if (yv[k].y) jmin = j0 + 1;
                else if (yv[k].z) jmin = j0 + 2;
                else              jmin = j0 + 3;
            }
        }
        if (ypeel && lane < jmin) jmin = lane;
        if (ytail && jmin == JINF) jmin = ts + lane;
        // rare overflow: columns not covered by the register batch
        for (int i = NCH * 32 + lane; i < nv; i += 32) {
            const int4 yo = __ldg((const int4*)(yr + p + 4 * i));
            if ((yo.x | yo.y | yo.z | yo.w) && jmin == JINF) {
                const int j0 = p + 4 * i;
                if      (yo.x) jmin = j0;
                else if (yo.y) jmin = j0 + 1;
                else if (yo.z) jmin = j0 + 2;
                else           jmin = j0 + 3;
            }
        }
        #pragma unroll
        for (int off = 16; off > 0; off >>= 1)
            jmin = min(jmin, __shfl_xor_sync(0xffffffffu, jmin, off));

        if (jmin != JINF) {
            // ---- wl row: group-masked max from register-held x ----
            const int fl = (int)(((unsigned)jmin * M) >> 22);
            const int lo = fl * gs;
            const int hi = min(lo + gs, n);
            float m = -1e30f;
            if (lane < p && lane >= lo && lane < hi) m = fmaxf(m, xpeel);
            #pragma unroll
            for (int k = 0; k < NCH; k++) {
                const int j0 = p + 4 * (lane + k * 32);
                if (j0 + 3 >= lo && j0 < hi) {     // chunk overlaps group
                    if (j0     >= lo && j0     < hi) m = fmaxf(m, xv[k].x);
                    if (j0 + 1 >= lo && j0 + 1 < hi) m = fmaxf(m, xv[k].y);
                    if (j0 + 2 >= lo && j0 + 2 < hi) m = fmaxf(m, xv[k].z);
                    if (j0 + 3 >= lo && j0 + 3 < hi) m = fmaxf(m, xv[k].w);
                }
            }
            {
                const int j = ts + lane;
                if (lane < ntail && j >= lo && j < hi) m = fmaxf(m, xtail);
            }
            // rare overflow columns
            for (int i = NCH * 32 + lane; i < nv; i += 32) {
                const int j0 = p + 4 * i;
                if (j0 + 3 >= lo && j0 < hi) {
                    const float4 xo = __ldg((const float4*)(xr + p + 4 * i));
                    if (j0     >= lo && j0     < hi) m = fmaxf(m, xo.x);
                    if (j0 + 1 >= lo && j0 + 1 < hi) m = fmaxf(m, xo.y);
                    if (j0 + 2 >= lo && j0 + 2 < hi) m = fmaxf(m, xo.z);
                    if (j0 + 3 >= lo && j0 + 3 < hi) m = fmaxf(m, xo.w);
                }
            }
            #pragma unroll
            for (int off = 16; off > 0; off >>= 1)
                m = fmaxf(m, __shfl_xor_sync(0xffffffffu, m, off));
            warp_loss = rank_loss_(sigmoidf_(m), 0.5f);
        } else {
            // ---- other row: mN from registers; one yneg epoch for mW ----
            float mN = fmaxf(xpeel, xtail);
            #pragma unroll
            for (int k = 0; k < NCH; k++)
                mN = fmaxf(mN, fmaxf(fmaxf(xv[k].x, xv[k].y),
                                     fmaxf(xv[k].z, xv[k].w)));

            int4 nvv[NCH];
            const int npeel = (lane < p) ? __ldg(ynr + lane) : 0;
            const int ntl   = (lane < ntail) ? __ldg(ynr + ts + lane) : 0;
            #pragma unroll
            for (int k = 0; k < NCH; k++) {
                const int i = lane + k * 32;
                nvv[k] = (i < nvr) ? __ldg((const int4*)(ynr + p + 4 * i))
                                   : make_int4(0, 0, 0, 0);
            }
            float mW = -1e30f;
            if (npeel) mW = fmaxf(mW, xpeel);
            if (ntl)   mW = fmaxf(mW, xtail);
            #pragma unroll
            for (int k = 0; k < NCH; k++) {
                mW = fmaxf(mW, nvv[k].x ? xv[k].x : -1e30f);
                mW = fmaxf(mW, nvv[k].y ? xv[k].y : -1e30f);
                mW = fmaxf(mW, nvv[k].z ? xv[k].z : -1e30f);
                mW = fmaxf(mW, nvv[k].w ? xv[k].w : -1e30f);
            }
            // rare overflow columns
            for (int i = NCH * 32 + lane; i < nv; i += 32) {
                const float4 xo  = __ldg((const float4*)(xr  + p + 4 * i));
                const int4   no  = __ldg((const int4*)  (ynr + p + 4 * i));
                mN = fmaxf(mN, fmaxf(fmaxf(xo.x, xo.y), fmaxf(xo.z, xo.w)));
                mW = fmaxf(mW, no.x ? xo.x : -1e30f);
                mW = fmaxf(mW, no.y ? xo.y : -1e30f);
                mW = fmaxf(mW, no.z ? xo.z : -1e30f);
                mW = fmaxf(mW, no.w ? xo.w : -1e30f);
            }
            #pragma unroll
            for (int off = 16; off > 0; off >>= 1) {
                mN = fmaxf(mN, __shfl_xor_sync(0xffffffffu, mN, off));
                mW = fmaxf(mW, __shfl_xor_sync(0xffffffffu, mW, off));
            }
            warp_loss = 0.5f * rank_loss_(0.5f, sigmoidf_(mN))
                      + 0.5f * rank_loss_(0.5f, sigmoidf_(mW));
        }
    } else if (row < B) {
        // ---------------- generic slow path (warp-per-row) ----------------
        const unsigned KNEG = enc_f(-1e30f);
        sG[wid][lane] = KNEG;
        __syncwarp();

        unsigned locNon = KNEG, locWrong = KNEG, locPres = 0u;
        for (int i = lane; i < n; i += 32) {
            const unsigned long long pk = g_pack[i];
            const int c         = (int)(pk & 0xffffffffull);
            const unsigned bits = (unsigned)(pk >> 32);
            const long long o = (long long)row * C + c;
            const float xvv = __ldg(x + o);
            const unsigned key = enc_f(xvv);
            locNon = max(locNon, key);
            if (__ldg(yneg + o) != 0) locWrong = max(locWrong, key);
            if (__ldg(y    + o) != 0) locPres |= bits;
            unsigned bb = bits;
            while (bb) {
                const int l = __ffs(bb) - 1;
                bb &= bb - 1u;
                atomicMax(&sG[wid][l], key);
            }
        }
        #pragma unroll
        for (int off = 16; off > 0; off >>= 1) {
            locNon   = max(locNon,   __shfl_xor_sync(0xffffffffu, locNon,   off));
            locWrong = max(locWrong, __shfl_xor_sync(0xffffffffu, locWrong, off));
            locPres |= __shfl_xor_sync(0xffffffffu, locPres, off);
        }
        __syncwarp();
        if (lane == 0) {
            if (locPres) {
                const int fl = __ffs(locPres) - 1;
                warp_loss = rank_loss_(sigmoidf_(dec_f(sG[wid][fl])), 0.5f);
            } else {
                warp_loss = 0.5f * rank_loss_(0.5f, sigmoidf_(dec_f(locNon)))
                          + 0.5f * rank_loss_(0.5f, sigmoidf_(dec_f(locWrong)));
            }
        }
    }

    if (lane == 0 && row < B) atomicAdd(&sSum, warp_loss);
    __syncthreads();
    if (threadIdx.x == 0) atomicAdd(out, sSum);
}

// ---------------------------------------------------------------------------
extern "C" void kernel_launch(void* const* d_in, const int* in_sizes, int n_in,
                              void* d_out, int out_size) {
    const float* x    = (const float*)d_in[0];
    const int*   y    = (const int*)d_in[1];
    const int*   yneg = (const int*)d_in[2];
    const void*  wl   = d_in[3];

    const int C = 9605;
    const int L = in_sizes[3] / C;            // 20
    const int B = in_sizes[0] / C;            // 4096

    float* out = (float*)d_out;

    init_kernel<<<1, 256>>>(out, out_size, (const unsigned int*)wl, 256);
    build_bits_kernel<<<(C + 255) / 256, 256>>>(wl, C, L);
    compact_kernel<<<(C + 255) / 256, 256>>>(C);
    row_loss_kernel<<<(B + 3) / 4, 128>>>(x, y, yneg, C, B, out);
}